// round 4
// baseline (speedup 1.0000x reference)
#include <cuda_runtime.h>
#include <cstdint>

#define Bb 16
#define Nn 16
#define Hh 512
#define Ww 512
#define HW4 (Hh * Ww / 4)          // 65536 float4 per slice
#define W4 (Ww / 4)                // 128 float4 per row
#define THREADS 256
#define NG 4                       // masks per block
#define NGROUPS (Nn / NG)          // 4
#define SPLIT 16
#define CHUNK_F4 (HW4 / SPLIT)     // 4096 float4 (= 32 rows)
#define ITER (CHUNK_F4 / THREADS)  // 16
#define GRID (Bb * NGROUPS * SPLIT) // 1024

__device__ float    g_ov[Bb * Nn];
__device__ float    g_it[Bb * Nn];
__device__ float    g_ts[Bb];
__device__ unsigned g_done;

__global__ __launch_bounds__(THREADS)
void fused2_kernel(const float* __restrict__ masks,
                   const float* __restrict__ target,
                   const int*   __restrict__ boxes,
                   float*       __restrict__ out)
{
    const int blk   = blockIdx.x;       // 0..1023
    const int b     = blk >> 6;
    const int rest  = blk & 63;
    const int ng    = rest >> 4;        // 0..3  (mask group)
    const int split = rest & 15;        // 0..15 (chunk)

    const int tid = threadIdx.x;
    const int wid = tid >> 5;
    const int lid = tid & 31;
    const unsigned FULL = 0xFFFFFFFFu;

    const size_t coff = (size_t)split * CHUNK_F4;
    const float4* __restrict__ t  = (const float4*)target + (size_t)b * HW4 + coff;
    const float4* __restrict__ m0 = (const float4*)masks + ((size_t)(b * Nn + ng * NG + 0)) * HW4 + coff;
    const float4* __restrict__ m1 = (const float4*)masks + ((size_t)(b * Nn + ng * NG + 1)) * HW4 + coff;
    const float4* __restrict__ m2 = (const float4*)masks + ((size_t)(b * Nn + ng * NG + 2)) * HW4 + coff;
    const float4* __restrict__ m3 = (const float4*)masks + ((size_t)(b * Nn + ng * NG + 3)) * HW4 + coff;

    // per-thread column position (k-invariant) and base row
    const int w0 = (tid & (W4 - 1)) << 2;
    const int h0 = split * (CHUNK_F4 / W4) + (tid >> 7);   // k adds 2 rows

    // per-mask box data: column selectors + row range
    float c0[NG], c1[NG], c2[NG], c3[NG];
    int   y1[NG], y2[NG];
    #pragma unroll
    for (int j = 0; j < NG; j++) {
        const int4 bx = __ldg((const int4*)boxes + b * Nn + ng * NG + j);
        y1[j] = bx.y; y2[j] = bx.w;
        c0[j] = (w0     >= bx.x && w0     < bx.z) ? 1.f : 0.f;
        c1[j] = (w0 + 1 >= bx.x && w0 + 1 < bx.z) ? 1.f : 0.f;
        c2[j] = (w0 + 2 >= bx.x && w0 + 2 < bx.z) ? 1.f : 0.f;
        c3[j] = (w0 + 3 >= bx.x && w0 + 3 < bx.z) ? 1.f : 0.f;
    }

    float ov[NG] = {0.f, 0.f, 0.f, 0.f};
    float it[NG] = {0.f, 0.f, 0.f, 0.f};
    float ts = 0.f;

    #pragma unroll 4
    for (int k = 0; k < ITER; k++) {
        const int idx = tid + k * THREADS;
        const float4 tv = t[idx];
        const float4 v0 = m0[idx];
        const float4 v1 = m1[idx];
        const float4 v2 = m2[idx];
        const float4 v3 = m3[idx];

        const int h = h0 + 2 * k;
        ts += (tv.x + tv.y) + (tv.z + tv.w);

        ov[0] = fmaf(v0.x, tv.x, ov[0]); ov[0] = fmaf(v0.y, tv.y, ov[0]);
        ov[0] = fmaf(v0.z, tv.z, ov[0]); ov[0] = fmaf(v0.w, tv.w, ov[0]);
        ov[1] = fmaf(v1.x, tv.x, ov[1]); ov[1] = fmaf(v1.y, tv.y, ov[1]);
        ov[1] = fmaf(v1.z, tv.z, ov[1]); ov[1] = fmaf(v1.w, tv.w, ov[1]);
        ov[2] = fmaf(v2.x, tv.x, ov[2]); ov[2] = fmaf(v2.y, tv.y, ov[2]);
        ov[2] = fmaf(v2.z, tv.z, ov[2]); ov[2] = fmaf(v2.w, tv.w, ov[2]);
        ov[3] = fmaf(v3.x, tv.x, ov[3]); ov[3] = fmaf(v3.y, tv.y, ov[3]);
        ov[3] = fmaf(v3.z, tv.z, ov[3]); ov[3] = fmaf(v3.w, tv.w, ov[3]);

        #pragma unroll
        for (int j = 0; j < NG; j++) {
            if (h >= y1[j] && h < y2[j]) {        // warp-uniform branch
                float s;
                s = fmaf(c0[j], tv.x, 0.f);
                s = fmaf(c1[j], tv.y, s);
                s = fmaf(c2[j], tv.z, s);
                s = fmaf(c3[j], tv.w, s);
                it[j] += s;
            }
        }
    }

    // ---- single end-of-block reduction of 9 values ----
    float v[9] = {ov[0], ov[1], ov[2], ov[3], it[0], it[1], it[2], it[3], ts};
    #pragma unroll
    for (int q = 0; q < 9; q++) {
        #pragma unroll
        for (int off = 16; off > 0; off >>= 1)
            v[q] += __shfl_xor_sync(FULL, v[q], off);
    }

    __shared__ float s_red[THREADS / 32][9];
    if (lid == 0) {
        #pragma unroll
        for (int q = 0; q < 9; q++) s_red[wid][q] = v[q];
    }
    __syncthreads();

    if (tid < 9) {
        float sum = 0.f;
        #pragma unroll
        for (int w = 0; w < THREADS / 32; w++) sum += s_red[w][tid];
        if (tid < 4) {
            atomicAdd(&g_ov[b * Nn + ng * NG + tid], sum);
        } else if (tid < 8) {
            atomicAdd(&g_it[b * Nn + ng * NG + (tid - 4)], sum);
        } else if (ng == 0) {      // target sum counted once per (b, chunk)
            atomicAdd(&g_ts[b], sum);
        }
    }
    __threadfence();
    __syncthreads();

    __shared__ unsigned s_last;
    if (tid == 0) s_last = atomicAdd(&g_done, 1u);
    __syncthreads();

    // ---- last block finalizes + resets ----
    if (s_last == GRID - 1) {
        const int bn = tid;   // 0..255
        const float ovv = *(volatile float*)&g_ov[bn];
        const float itv = *(volatile float*)&g_it[bn];
        const float tsv = *(volatile float*)&g_ts[bn >> 4];
        const int4 bx = reinterpret_cast<const int4*>(boxes)[bn];
        const float area = (float)(bx.z - bx.x) * (float)(bx.w - bx.y);
        const float uni = area + tsv - itv;
        out[bn * 2 + 0] = ovv;
        out[bn * 2 + 1] = itv / (uni + 1e-8f);
        g_ov[bn] = 0.f;
        g_it[bn] = 0.f;
        if (bn < Bb) g_ts[bn] = 0.f;
        if (bn == 0) g_done = 0u;
    }
}

extern "C" void kernel_launch(void* const* d_in, const int* in_sizes, int n_in,
                              void* d_out, int out_size)
{
    const float* masks  = (const float*)d_in[0];   // (B,N,H,W) f32
    const float* target = (const float*)d_in[1];   // (B,H,W)   f32
    const int*   boxes  = (const int*)d_in[2];     // (B,N,4)   i32
    float* out = (float*)d_out;                    // (B,N,2)   f32

    fused2_kernel<<<GRID, THREADS>>>(masks, target, boxes, out);
}